// round 1
// baseline (speedup 1.0000x reference)
#include <cuda_runtime.h>
#include <math.h>

#define BB 4
#define SS 1024
#define DD 1024
#define HH 16
#define DK 64
#define MM (BB*SS)   // 4096

// Scratch (allocation-free rule: __device__ globals)
__device__ float g_Q[BB*HH*SS*DK];
__device__ float g_K[BB*HH*SS*DK];
__device__ float g_V[BB*HH*SS*DK];
__device__ float g_ctx[(size_t)MM*DD];
__device__ float g_x[(size_t)MM*DD];

// ---------------------------------------------------------------------------
// GEMM: C = A[M,K=1024] @ W^T (W is [N,K=1024], K-contiguous both) + bias
// 128x128 block tile, 16x16 threads, 8x8 per thread, BK=16.
// QKV_REMAP: write into [B,H,S,dk].  ADD_RES: add residual (v) before store.
// ---------------------------------------------------------------------------
template<int QKV_REMAP, int ADD_RES>
__global__ __launch_bounds__(256) void gemm_xwt(
    const float* __restrict__ A,
    const float* __restrict__ W,
    const float* __restrict__ bias,
    const float* __restrict__ res,
    float* __restrict__ C)
{
    const int K = 1024;
    __shared__ float As[16][132];
    __shared__ float Ws[16][132];

    const int tid = threadIdx.x;
    const int tx = tid & 15;
    const int ty = tid >> 4;
    const int m0 = blockIdx.y * 128;
    const int n0 = blockIdx.x * 128;

    float acc[8][8];
#pragma unroll
    for (int i = 0; i < 8; i++)
#pragma unroll
        for (int j = 0; j < 8; j++) acc[i][j] = 0.f;

    const int lr = tid >> 2;        // 0..63
    const int lk = (tid & 3) * 4;   // 0,4,8,12

    for (int kk = 0; kk < K; kk += 16) {
#pragma unroll
        for (int h = 0; h < 2; h++) {
            int r = lr + h * 64;
            float4 va = *(const float4*)(A + (size_t)(m0 + r) * K + kk + lk);
            As[lk + 0][r] = va.x; As[lk + 1][r] = va.y;
            As[lk + 2][r] = va.z; As[lk + 3][r] = va.w;
            float4 vw = *(const float4*)(W + (size_t)(n0 + r) * K + kk + lk);
            Ws[lk + 0][r] = vw.x; Ws[lk + 1][r] = vw.y;
            Ws[lk + 2][r] = vw.z; Ws[lk + 3][r] = vw.w;
        }
        __syncthreads();
#pragma unroll
        for (int k = 0; k < 16; k++) {
            float a[8], b[8];
            *(float4*)(a)     = *(const float4*)&As[k][ty * 8];
            *(float4*)(a + 4) = *(const float4*)&As[k][ty * 8 + 4];
            *(float4*)(b)     = *(const float4*)&Ws[k][tx * 8];
            *(float4*)(b + 4) = *(const float4*)&Ws[k][tx * 8 + 4];
#pragma unroll
            for (int i = 0; i < 8; i++)
#pragma unroll
                for (int j = 0; j < 8; j++)
                    acc[i][j] = fmaf(a[i], b[j], acc[i][j]);
        }
        __syncthreads();
    }

#pragma unroll
    for (int i = 0; i < 8; i++) {
        int m = m0 + ty * 8 + i;
        int bi = m >> 10;       // /S
        int si = m & 1023;      // %S
#pragma unroll
        for (int jj = 0; jj < 8; jj += 4) {
            int n = n0 + tx * 8 + jj;
            float4 bv = *(const float4*)(bias + n);
            float4 r;
            r.x = acc[i][jj + 0] + bv.x;
            r.y = acc[i][jj + 1] + bv.y;
            r.z = acc[i][jj + 2] + bv.z;
            r.w = acc[i][jj + 3] + bv.w;
            if (ADD_RES) {
                float4 rv = *(const float4*)(res + (size_t)m * DD + n);
                r.x += rv.x; r.y += rv.y; r.z += rv.z; r.w += rv.w;
            }
            if (QKV_REMAP) {
                int h = n >> 6;     // /dk
                int d = n & 63;     // %dk
                *(float4*)(C + (((size_t)(bi * HH + h) * SS + si) * DK + d)) = r;
            } else {
                *(float4*)(C + (size_t)m * DD + n) = r;
            }
        }
    }
}

// ---------------------------------------------------------------------------
// Scores: attn[bh, s, t] = dot(Q[bh,s,:], K[bh,t,:]) / 8   (per-head batched)
// 64x64 tile per block, full K=64 staged in shared.
// ---------------------------------------------------------------------------
__global__ __launch_bounds__(256) void scores_kernel(
    const float* __restrict__ Q, const float* __restrict__ Km,
    float* __restrict__ attn)
{
    __shared__ float Qs[64][64];
    __shared__ float Ks[64][64];

    const int bh = blockIdx.z;
    const float* Qh = Q  + (size_t)bh * SS * DK;
    const float* Kh = Km + (size_t)bh * SS * DK;
    const int s0 = blockIdx.y * 64;
    const int t0 = blockIdx.x * 64;
    const int tid = threadIdx.x;
    const int tx = tid & 15;
    const int ty = tid >> 4;

    const int lr = tid >> 2;          // 0..63
    const int lc = (tid & 3) * 16;    // 0,16,32,48
#pragma unroll
    for (int u = 0; u < 16; u += 4) {
        *(float4*)&Qs[lr][lc + u] = *(const float4*)(Qh + (size_t)(s0 + lr) * DK + lc + u);
        *(float4*)&Ks[lr][lc + u] = *(const float4*)(Kh + (size_t)(t0 + lr) * DK + lc + u);
    }
    __syncthreads();

    float acc[4][4];
#pragma unroll
    for (int i = 0; i < 4; i++)
#pragma unroll
        for (int j = 0; j < 4; j++) acc[i][j] = 0.f;

#pragma unroll
    for (int k4 = 0; k4 < 16; k4++) {
        float4 qa[4], kb[4];
#pragma unroll
        for (int i = 0; i < 4; i++) qa[i] = *(const float4*)&Qs[ty * 4 + i][k4 * 4];
#pragma unroll
        for (int j = 0; j < 4; j++) kb[j] = *(const float4*)&Ks[tx * 4 + j][k4 * 4];
#pragma unroll
        for (int i = 0; i < 4; i++)
#pragma unroll
            for (int j = 0; j < 4; j++) {
                acc[i][j] = fmaf(qa[i].x, kb[j].x, acc[i][j]);
                acc[i][j] = fmaf(qa[i].y, kb[j].y, acc[i][j]);
                acc[i][j] = fmaf(qa[i].z, kb[j].z, acc[i][j]);
                acc[i][j] = fmaf(qa[i].w, kb[j].w, acc[i][j]);
            }
    }

#pragma unroll
    for (int i = 0; i < 4; i++) {
        size_t off = ((size_t)bh * SS + (s0 + ty * 4 + i)) * SS + t0 + tx * 4;
        float4 r;
        r.x = acc[i][0] * 0.125f; r.y = acc[i][1] * 0.125f;
        r.z = acc[i][2] * 0.125f; r.w = acc[i][3] * 0.125f;
        *(float4*)(attn + off) = r;
    }
}

// ---------------------------------------------------------------------------
// Softmax (in place on attn), mask applied here (mask[b,s,t] -> -1e30).
// One block per row (b,h,s). 256 threads x 4 elems.
// ---------------------------------------------------------------------------
__device__ __forceinline__ float warpMax(float v) {
#pragma unroll
    for (int o = 16; o; o >>= 1) v = fmaxf(v, __shfl_xor_sync(0xffffffffu, v, o));
    return v;
}
__device__ __forceinline__ float warpSum(float v) {
#pragma unroll
    for (int o = 16; o; o >>= 1) v += __shfl_xor_sync(0xffffffffu, v, o);
    return v;
}

__global__ __launch_bounds__(256) void softmax_kernel(
    float* __restrict__ attn, const unsigned char* __restrict__ mask)
{
    __shared__ float red[8];
    const int row = blockIdx.x;          // bh*S + s
    const int bh = row >> 10;
    const int s  = row & 1023;
    const int b  = bh >> 4;
    float* p = attn + (size_t)row * SS;
    const unsigned char* mr = mask + ((size_t)(b * SS + s)) * SS;
    const int t = threadIdx.x;

    float4 v = *(const float4*)(p + t * 4);
    uchar4 mk = *(const uchar4*)(mr + t * 4);
    if (mk.x) v.x = -1e30f;
    if (mk.y) v.y = -1e30f;
    if (mk.z) v.z = -1e30f;
    if (mk.w) v.w = -1e30f;

    float mx = fmaxf(fmaxf(v.x, v.y), fmaxf(v.z, v.w));
    mx = warpMax(mx);
    if ((t & 31) == 0) red[t >> 5] = mx;
    __syncthreads();
    if (t < 32) {
        float q = (t < 8) ? red[t] : -1e30f;
        q = warpMax(q);
        if (t == 0) red[0] = q;
    }
    __syncthreads();
    mx = red[0];

    float4 e;
    e.x = expf(v.x - mx); e.y = expf(v.y - mx);
    e.z = expf(v.z - mx); e.w = expf(v.w - mx);
    float sm = e.x + e.y + e.z + e.w;
    sm = warpSum(sm);
    __syncthreads();
    if ((t & 31) == 0) red[t >> 5] = sm;
    __syncthreads();
    if (t < 32) {
        float q = (t < 8) ? red[t] : 0.f;
        q = warpSum(q);
        if (t == 0) red[0] = q;
    }
    __syncthreads();
    float inv = 1.0f / red[0];

    float4 r;
    r.x = e.x * inv; r.y = e.y * inv; r.z = e.z * inv; r.w = e.w * inv;
    *(float4*)(p + t * 4) = r;
}

// ---------------------------------------------------------------------------
// Context: ctx[b,s,h*64+d] = sum_t attn[bh,s,t] * V[bh,t,d]
// Per-head GEMM M=1024, N=64, K=1024. 64x64 tile, BK=32.
// ---------------------------------------------------------------------------
__global__ __launch_bounds__(256) void context_kernel(
    const float* __restrict__ attn, const float* __restrict__ V,
    float* __restrict__ ctx)
{
    __shared__ float As[32][65];   // [t][s]
    __shared__ float Vs[32][64];   // [t][d]

    const int bh = blockIdx.y;
    const int b = bh >> 4;
    const int h = bh & 15;
    const int s0 = blockIdx.x * 64;
    const float* Ah = attn + (size_t)bh * SS * SS;
    const float* Vh = V    + (size_t)bh * SS * DK;

    const int tid = threadIdx.x;
    const int tx = tid & 15;
    const int ty = tid >> 4;

    float4 acc[4];
#pragma unroll
    for (int i = 0; i < 4; i++) acc[i] = make_float4(0.f, 0.f, 0.f, 0.f);

    const int lrA = tid >> 2;          // 0..63 (s)
    const int lcA = (tid & 3) * 8;     // t group
    const int lrV = tid >> 3;          // 0..31 (t)
    const int lcV = (tid & 7) * 8;     // d group

    for (int kt = 0; kt < SS; kt += 32) {
#pragma unroll
        for (int u = 0; u < 8; u += 4) {
            float4 va = *(const float4*)(Ah + (size_t)(s0 + lrA) * SS + kt + lcA + u);
            As[lcA + u + 0][lrA] = va.x; As[lcA + u + 1][lrA] = va.y;
            As[lcA + u + 2][lrA] = va.z; As[lcA + u + 3][lrA] = va.w;
            *(float4*)&Vs[lrV][lcV + u] = *(const float4*)(Vh + (size_t)(kt + lrV) * DK + lcV + u);
        }
        __syncthreads();
#pragma unroll
        for (int k = 0; k < 32; k++) {
            float4 vb = *(const float4*)&Vs[k][tx * 4];
#pragma unroll
            for (int i = 0; i < 4; i++) {
                float a = As[k][ty * 4 + i];
                acc[i].x = fmaf(a, vb.x, acc[i].x);
                acc[i].y = fmaf(a, vb.y, acc[i].y);
                acc[i].z = fmaf(a, vb.z, acc[i].z);
                acc[i].w = fmaf(a, vb.w, acc[i].w);
            }
        }
        __syncthreads();
    }

#pragma unroll
    for (int i = 0; i < 4; i++) {
        int s = s0 + ty * 4 + i;
        *(float4*)(ctx + ((size_t)(b * SS + s)) * DD + h * DK + tx * 4) = acc[i];
    }
}

// ---------------------------------------------------------------------------
// LayerNorm: one block per row of 1024.
// ---------------------------------------------------------------------------
__global__ __launch_bounds__(256) void ln_kernel(
    const float* __restrict__ x, const float* __restrict__ g,
    const float* __restrict__ bb, float* __restrict__ out)
{
    __shared__ float redA[8];
    __shared__ float redB[8];
    const int row = blockIdx.x;
    const int t = threadIdx.x;
    float4 v = *(const float4*)(x + (size_t)row * DD + t * 4);

    float s  = v.x + v.y + v.z + v.w;
    float s2 = v.x * v.x + v.y * v.y + v.z * v.z + v.w * v.w;
    s = warpSum(s); s2 = warpSum(s2);
    if ((t & 31) == 0) { redA[t >> 5] = s; redB[t >> 5] = s2; }
    __syncthreads();
    if (t < 32) {
        float a = (t < 8) ? redA[t] : 0.f;
        float c = (t < 8) ? redB[t] : 0.f;
        a = warpSum(a); c = warpSum(c);
        if (t == 0) { redA[0] = a; redB[0] = c; }
    }
    __syncthreads();
    float mu  = redA[0] * (1.0f / 1024.0f);
    float var = redB[0] * (1.0f / 1024.0f) - mu * mu;
    float inv = rsqrtf(var + 1e-6f);

    float4 gv = *(const float4*)(g + t * 4);
    float4 bv = *(const float4*)(bb + t * 4);
    float4 r;
    r.x = (v.x - mu) * inv * gv.x + bv.x;
    r.y = (v.y - mu) * inv * gv.y + bv.y;
    r.z = (v.z - mu) * inv * gv.z + bv.z;
    r.w = (v.w - mu) * inv * gv.w + bv.w;
    *(float4*)(out + (size_t)row * DD + t * 4) = r;
}

// ---------------------------------------------------------------------------
extern "C" void kernel_launch(void* const* d_in, const int* in_sizes, int n_in,
                              void* d_out, int out_size)
{
    const float* q    = (const float*)d_in[0];
    const float* k    = (const float*)d_in[1];
    const float* v    = (const float*)d_in[2];
    const unsigned char* mask = (const unsigned char*)d_in[3];
    const float* Wq   = (const float*)d_in[4];
    const float* bq   = (const float*)d_in[5];
    const float* Wk   = (const float*)d_in[6];
    const float* bk   = (const float*)d_in[7];
    const float* Wv   = (const float*)d_in[8];
    const float* bv   = (const float*)d_in[9];
    const float* Wo   = (const float*)d_in[10];
    const float* bo   = (const float*)d_in[11];
    const float* ln_g = (const float*)d_in[12];
    const float* ln_b = (const float*)d_in[13];

    float* out_norm = (float*)d_out;
    float* attn = (float*)d_out + (size_t)MM * DD;   // attns region of output

    float *pQ, *pK, *pV, *pCtx, *pX;
    cudaGetSymbolAddress((void**)&pQ,   g_Q);
    cudaGetSymbolAddress((void**)&pK,   g_K);
    cudaGetSymbolAddress((void**)&pV,   g_V);
    cudaGetSymbolAddress((void**)&pCtx, g_ctx);
    cudaGetSymbolAddress((void**)&pX,   g_x);

    dim3 gGemm(DD / 128, MM / 128);   // (8, 32)
    gemm_xwt<1, 0><<<gGemm, 256>>>(q, Wq, bq, nullptr, pQ);
    gemm_xwt<1, 0><<<gGemm, 256>>>(k, Wk, bk, nullptr, pK);
    gemm_xwt<1, 0><<<gGemm, 256>>>(v, Wv, bv, nullptr, pV);

    dim3 gSc(SS / 64, SS / 64, BB * HH);   // (16,16,64)
    scores_kernel<<<gSc, 256>>>(pQ, pK, attn);

    softmax_kernel<<<BB * HH * SS, 256>>>(attn, mask);

    dim3 gCtx(SS / 64, BB * HH);           // (16,64)
    context_kernel<<<gCtx, 256>>>(attn, pV, pCtx);

    gemm_xwt<0, 1><<<gGemm, 256>>>(pCtx, Wo, bo, v, pX);

    ln_kernel<<<MM, 256>>>(pX, ln_g, ln_b, out_norm);
}

// round 3
// speedup vs baseline: 2.9196x; 2.9196x over previous
#include <cuda_runtime.h>
#include <cuda_bf16.h>
#include <cstdint>
#include <math.h>

#define BB 4
#define SS 1024
#define DD 1024
#define HH 16
#define DK 64
#define MM (BB*SS)   // 4096

// ---------------- scratch (__device__ globals; no allocation) ---------------
// pre-split inputs
__device__ __nv_bfloat16 g_qh[(size_t)MM*DD];
__device__ __nv_bfloat16 g_ql[(size_t)MM*DD];
__device__ __nv_bfloat16 g_kh[(size_t)MM*DD];
__device__ __nv_bfloat16 g_kl[(size_t)MM*DD];
__device__ __nv_bfloat16 g_vh[(size_t)MM*DD];
__device__ __nv_bfloat16 g_vl[(size_t)MM*DD];
// pre-split weights
__device__ __nv_bfloat16 g_wqh[(size_t)DD*DD];
__device__ __nv_bfloat16 g_wql[(size_t)DD*DD];
__device__ __nv_bfloat16 g_wkh[(size_t)DD*DD];
__device__ __nv_bfloat16 g_wkl[(size_t)DD*DD];
__device__ __nv_bfloat16 g_wvh[(size_t)DD*DD];
__device__ __nv_bfloat16 g_wvl[(size_t)DD*DD];
__device__ __nv_bfloat16 g_woh[(size_t)DD*DD];
__device__ __nv_bfloat16 g_wol[(size_t)DD*DD];
// projected Q/K/V in [B,H,S,dk], split
__device__ __nv_bfloat16 g_Qh[(size_t)MM*DD];
__device__ __nv_bfloat16 g_Ql[(size_t)MM*DD];
__device__ __nv_bfloat16 g_Kh[(size_t)MM*DD];
__device__ __nv_bfloat16 g_Kl[(size_t)MM*DD];
__device__ __nv_bfloat16 g_Vh[(size_t)MM*DD];
__device__ __nv_bfloat16 g_Vl[(size_t)MM*DD];
// context, split
__device__ __nv_bfloat16 g_Ch[(size_t)MM*DD];
__device__ __nv_bfloat16 g_Cl[(size_t)MM*DD];
// pre-LN activations
__device__ float g_x[(size_t)MM*DD];

// ---------------- helpers ----------------------------------------------------
__device__ __forceinline__ uint32_t smem_u32(const void* ptr) {
    return (uint32_t)__cvta_generic_to_shared(ptr);
}
__device__ __forceinline__ void ldsm4(uint32_t* dst, uint32_t addr) {
    asm volatile("ldmatrix.sync.aligned.m8n8.x4.shared.b16 {%0,%1,%2,%3},[%4];"
                 : "=r"(dst[0]), "=r"(dst[1]), "=r"(dst[2]), "=r"(dst[3]) : "r"(addr));
}
__device__ __forceinline__ void ldsm4t(uint32_t* dst, uint32_t addr) {
    asm volatile("ldmatrix.sync.aligned.m8n8.x4.trans.shared.b16 {%0,%1,%2,%3},[%4];"
                 : "=r"(dst[0]), "=r"(dst[1]), "=r"(dst[2]), "=r"(dst[3]) : "r"(addr));
}
__device__ __forceinline__ void mma16816(float* cc, const uint32_t* aa, const uint32_t* bb2) {
    asm volatile("mma.sync.aligned.m16n8k16.row.col.f32.bf16.bf16.f32 "
                 "{%0,%1,%2,%3},{%4,%5,%6,%7},{%8,%9},{%0,%1,%2,%3};"
                 : "+f"(cc[0]), "+f"(cc[1]), "+f"(cc[2]), "+f"(cc[3])
                 : "r"(aa[0]), "r"(aa[1]), "r"(aa[2]), "r"(aa[3]), "r"(bb2[0]), "r"(bb2[1]));
}
__device__ __forceinline__ void splitbf(float xin, __nv_bfloat16& ho, __nv_bfloat16& lo) {
    ho = __float2bfloat16(xin);
    lo = __float2bfloat16(xin - __bfloat162float(ho));
}
__device__ __forceinline__ float wredMax(float wv) {
#pragma unroll
    for (int wo = 16; wo; wo >>= 1) wv = fmaxf(wv, __shfl_xor_sync(0xffffffffu, wv, wo));
    return wv;
}
__device__ __forceinline__ float wredSum(float wv) {
#pragma unroll
    for (int wo = 16; wo; wo >>= 1) wv += __shfl_xor_sync(0xffffffffu, wv, wo);
    return wv;
}

// =============================================================================
// Pre-split fp32 -> bf16 hi/lo (grid-stride, float4)
// =============================================================================
__global__ __launch_bounds__(256) void split_kernel(
    const float* __restrict__ src,
    __nv_bfloat16* __restrict__ dh,
    __nv_bfloat16* __restrict__ dl,
    int nElem)
{
    int i4 = (blockIdx.x * 256 + threadIdx.x) * 4;
    int stride = gridDim.x * 256 * 4;
    for (; i4 < nElem; i4 += stride) {
        float4 sv = *(const float4*)(src + i4);
        __nv_bfloat16 sh0, sh1, sh2, sh3, sl0, sl1, sl2, sl3;
        splitbf(sv.x, sh0, sl0); splitbf(sv.y, sh1, sl1);
        splitbf(sv.z, sh2, sl2); splitbf(sv.w, sh3, sl3);
        *(__nv_bfloat162*)(dh + i4)     = __halves2bfloat162(sh0, sh1);
        *(__nv_bfloat162*)(dh + i4 + 2) = __halves2bfloat162(sh2, sh3);
        *(__nv_bfloat162*)(dl + i4)     = __halves2bfloat162(sl0, sl1);
        *(__nv_bfloat162*)(dl + i4 + 2) = __halves2bfloat162(sl2, sl3);
    }
}

// =============================================================================
// GEMM: C = A[4096,1024] @ W^T (+bias) (+res).  A,W pre-split bf16 hi/lo.
// Block 128x128, BK=32, 8 warps (2x4), warp tile 64x32, 3-pass split MMA.
// QKV_OUT=1: bf16 hi/lo out remapped to [B,H,S,dk]. Else fp32 out.
// =============================================================================
template<int QKV_OUT, int ADD_RES>
__global__ __launch_bounds__(256) void gemm_tc(
    const __nv_bfloat16* __restrict__ Ah,
    const __nv_bfloat16* __restrict__ Al,
    const __nv_bfloat16* __restrict__ Wh,
    const __nv_bfloat16* __restrict__ Wl,
    const float* __restrict__ bias,
    const float* __restrict__ res,
    __nv_bfloat16* __restrict__ Oh,
    __nv_bfloat16* __restrict__ Ol,
    float* __restrict__ Of)
{
    __shared__ __align__(16) __nv_bfloat16 sAh[128][40];
    __shared__ __align__(16) __nv_bfloat16 sAl[128][40];
    __shared__ __align__(16) __nv_bfloat16 sWh[128][40];
    __shared__ __align__(16) __nv_bfloat16 sWl[128][40];

    const int tid  = threadIdx.x;
    const int lane = tid & 31;
    const int wid  = tid >> 5;
    const int wm   = wid >> 2;   // 0..1
    const int wn   = wid & 3;    // 0..3
    const int m0   = blockIdx.y * 128;
    const int n0   = blockIdx.x * 128;

    float acc[4][4][4];
#pragma unroll
    for (int im = 0; im < 4; im++)
#pragma unroll
        for (int jn = 0; jn < 4; jn++)
#pragma unroll
            for (int qq = 0; qq < 4; qq++) acc[im][jn][qq] = 0.f;

    for (int kk = 0; kk < 1024; kk += 32) {
#pragma unroll
        for (int qq = 0; qq < 2; qq++) {
            int lin = tid + qq * 256;
            int srow = lin >> 2;
            int scol = (lin & 3) * 8;
            size_t offA = (size_t)(m0 + srow) * 1024 + kk + scol;
            size_t offW = (size_t)(n0 + srow) * 1024 + kk + scol;
            *(uint4*)&sAh[srow][scol] = *(const uint4*)(Ah + offA);
            *(uint4*)&sAl[srow][scol] = *(const uint4*)(Al + offA);
            *(uint4*)&sWh[srow][scol] = *(const uint4*)(Wh + offW);
            *(uint4*)&sWl[srow][scol] = *(const uint4*)(Wl + offW);
        }
        __syncthreads();

#pragma unroll
        for (int ks = 0; ks < 32; ks += 16) {
            uint32_t fAh[4][4], fAl[4][4], fBh[4][2], fBl[4][2];
#pragma unroll
            for (int mt = 0; mt < 4; mt++) {
                int ra = wm * 64 + mt * 16 + (lane & 15);
                int ca = ks + (lane >> 4) * 8;
                ldsm4(fAh[mt], smem_u32(&sAh[ra][ca]));
                ldsm4(fAl[mt], smem_u32(&sAl[ra][ca]));
            }
#pragma unroll
            for (int pp = 0; pp < 2; pp++) {
                int rb = wn * 32 + pp * 16 + ((lane >> 4) & 1) * 8 + (lane & 7);
                int cb = ks + ((lane >> 3) & 1) * 8;
                ldsm4(&fBh[2 * pp][0], smem_u32(&sWh[rb][cb]));
                ldsm4(&fBl[2 * pp][0], smem_u32(&sWl[rb][cb]));
            }
#pragma unroll
            for (int mt = 0; mt < 4; mt++)
#pragma unroll
                for (int nt = 0; nt < 4; nt++) {
                    mma16816(acc[mt][nt], fAh[mt], fBh[nt]);
                    mma16816(acc[mt][nt], fAh[mt], fBl[nt]);
                    mma16816(acc[mt][nt], fAl[mt], fBh[nt]);
                }
        }
        __syncthreads();
    }

    const int cg = lane >> 2;
    const int ct = lane & 3;
#pragma unroll
    for (int mt = 0; mt < 4; mt++)
#pragma unroll
        for (int nt = 0; nt < 4; nt++) {
            int nn = n0 + wn * 32 + nt * 8 + 2 * ct;
            float bv0 = bias[nn];
            float bv1 = bias[nn + 1];
#pragma unroll
            for (int hrow = 0; hrow < 2; hrow++) {
                int mmv = m0 + wm * 64 + mt * 16 + cg + hrow * 8;
                float ov0 = acc[mt][nt][hrow * 2 + 0] + bv0;
                float ov1 = acc[mt][nt][hrow * 2 + 1] + bv1;
                if (ADD_RES) {
                    float2 rres = *(const float2*)(res + (size_t)mmv * 1024 + nn);
                    ov0 += rres.x;
                    ov1 += rres.y;
                }
                if (QKV_OUT) {
                    int obi = mmv >> 10;
                    int osi = mmv & 1023;
                    int ohh = nn >> 6;
                    int odd = nn & 63;
                    size_t oidx = (((size_t)(obi * HH + ohh)) * SS + osi) * DK + odd;
                    __nv_bfloat16 zh0, zl0, zh1, zl1;
                    splitbf(ov0, zh0, zl0);
                    splitbf(ov1, zh1, zl1);
                    *(__nv_bfloat162*)(Oh + oidx) = __halves2bfloat162(zh0, zh1);
                    *(__nv_bfloat162*)(Ol + oidx) = __halves2bfloat162(zl0, zl1);
                } else {
                    *(float2*)(Of + (size_t)mmv * 1024 + nn) = make_float2(ov0, ov1);
                }
            }
        }
}

// =============================================================================
// Scores: per head, S[s,t] = (Q[s,:].K[t,:]) / 8.  M=N=1024, K=64, 64 heads.
// =============================================================================
__global__ __launch_bounds__(256) void scores_tc(
    const __nv_bfloat16* __restrict__ Qh, const __nv_bfloat16* __restrict__ Ql,
    const __nv_bfloat16* __restrict__ Kh, const __nv_bfloat16* __restrict__ Kl,
    float* __restrict__ attn)
{
    __shared__ __align__(16) __nv_bfloat16 sQh[128][40];
    __shared__ __align__(16) __nv_bfloat16 sQl[128][40];
    __shared__ __align__(16) __nv_bfloat16 sKh[128][40];
    __shared__ __align__(16) __nv_bfloat16 sKl[128][40];

    const int tid  = threadIdx.x;
    const int lane = tid & 31;
    const int wid  = tid >> 5;
    const int wm   = wid >> 2;
    const int wn   = wid & 3;
    const int bhid = blockIdx.z;
    const int s0   = blockIdx.y * 128;
    const int t0   = blockIdx.x * 128;
    const size_t baseH = (size_t)bhid * SS * DK;

    float acc[4][4][4];
#pragma unroll
    for (int im = 0; im < 4; im++)
#pragma unroll
        for (int jn = 0; jn < 4; jn++)
#pragma unroll
            for (int qq = 0; qq < 4; qq++) acc[im][jn][qq] = 0.f;

#pragma unroll
    for (int kk = 0; kk < 64; kk += 32) {
#pragma unroll
        for (int qq = 0; qq < 2; qq++) {
            int lin = tid + qq * 256;
            int srow = lin >> 2;
            int scol = (lin & 3) * 8;
            size_t offQ = baseH + (size_t)(s0 + srow) * DK + kk + scol;
            size_t offK = baseH + (size_t)(t0 + srow) * DK + kk + scol;
            *(uint4*)&sQh[srow][scol] = *(const uint4*)(Qh + offQ);
            *(uint4*)&sQl[srow][scol] = *(const uint4*)(Ql + offQ);
            *(uint4*)&sKh[srow][scol] = *(const uint4*)(Kh + offK);
            *(uint4*)&sKl[srow][scol] = *(const uint4*)(Kl + offK);
        }
        __syncthreads();
#pragma unroll
        for (int ks = 0; ks < 32; ks += 16) {
            uint32_t fAh[4][4], fAl[4][4], fBh[4][2], fBl[4][2];
#pragma unroll
            for (int mt = 0; mt < 4; mt++) {
                int ra = wm * 64 + mt * 16 + (lane & 15);
                int ca = ks + (lane >> 4) * 8;
                ldsm4(fAh[mt], smem_u32(&sQh[ra][ca]));
                ldsm4(fAl[mt], smem_u32(&sQl[ra][ca]));
            }
#pragma unroll
            for (int pp = 0; pp < 2; pp++) {
                int rb = wn * 32 + pp * 16 + ((lane >> 4) & 1) * 8 + (lane & 7);
                int cb = ks + ((lane >> 3) & 1) * 8;
                ldsm4(&fBh[2 * pp][0], smem_u32(&sKh[rb][cb]));
                ldsm4(&fBl[2 * pp][0], smem_u32(&sKl[rb][cb]));
            }
#pragma unroll
            for (int mt = 0; mt < 4; mt++)
#pragma unroll
                for (int nt = 0; nt < 4; nt++) {
                    mma16816(acc[mt][nt], fAh[mt], fBh[nt]);
                    mma16816(acc[mt][nt], fAh[mt], fBl[nt]);
                    mma16816(acc[mt][nt], fAl[mt], fBh[nt]);
                }
        }
        __syncthreads();
    }

    const int cg = lane >> 2;
    const int ct = lane & 3;
#pragma unroll
    for (int mt = 0; mt < 4; mt++)
#pragma unroll
        for (int nt = 0; nt < 4; nt++) {
            int nn = t0 + wn * 32 + nt * 8 + 2 * ct;
#pragma unroll
            for (int hrow = 0; hrow < 2; hrow++) {
                int mmv = s0 + wm * 64 + mt * 16 + cg + hrow * 8;
                float ov0 = acc[mt][nt][hrow * 2 + 0] * 0.125f;
                float ov1 = acc[mt][nt][hrow * 2 + 1] * 0.125f;
                *(float2*)(attn + ((size_t)bhid * SS + mmv) * SS + nn) = make_float2(ov0, ov1);
            }
        }
}

// =============================================================================
// Softmax (in place, mask applied). One block per row.
// =============================================================================
__global__ __launch_bounds__(256) void softmax_kernel(
    float* __restrict__ attn, const unsigned char* __restrict__ mask)
{
    __shared__ float sred[8];
    const int row  = blockIdx.x;
    const int bhid = row >> 10;
    const int srow = row & 1023;
    const int bidx = bhid >> 4;
    float* prow = attn + (size_t)row * SS;
    const unsigned char* mrow = mask + ((size_t)(bidx * SS + srow)) * SS;
    const int tt = threadIdx.x;

    float4 xv = *(const float4*)(prow + tt * 4);
    uchar4 mk = *(const uchar4*)(mrow + tt * 4);
    if (mk.x) xv.x = -1e30f;
    if (mk.y) xv.y = -1e30f;
    if (mk.z) xv.z = -1e30f;
    if (mk.w) xv.w = -1e30f;

    float mx = fmaxf(fmaxf(xv.x, xv.y), fmaxf(xv.z, xv.w));
    mx = wredMax(mx);
    if ((tt & 31) == 0) sred[tt >> 5] = mx;
    __syncthreads();
    if (tt < 32) {
        float tmx = (tt < 8) ? sred[tt] : -1e30f;
        tmx = wredMax(tmx);
        if (tt == 0) sred[0] = tmx;
    }
    __syncthreads();
    mx = sred[0];

    float e0 = expf(xv.x - mx);
    float e1 = expf(xv.y - mx);
    float e2 = expf(xv.z - mx);
    float e3 = expf(xv.w - mx);
    float psum = e0 + e1 + e2 + e3;
    psum = wredSum(psum);
    __syncthreads();
    if ((tt & 31) == 0) sred[tt >> 5] = psum;
    __syncthreads();
    if (tt < 32) {
        float tsm = (tt < 8) ? sred[tt] : 0.f;
        tsm = wredSum(tsm);
        if (tt == 0) sred[0] = tsm;
    }
    __syncthreads();
    float inv = 1.0f / sred[0];

    *(float4*)(prow + tt * 4) = make_float4(e0 * inv, e1 * inv, e2 * inv, e3 * inv);
}

// =============================================================================
// Context: per head, ctx[s,d] = sum_t attn[s,t] * V[t,d].  M=1024,N=64,K=1024.
// attn fp32 split on load; V pre-split bf16 (ldmatrix.trans).
// Block 128(s) x 64(d), BK=32, 8 warps (4x2), warp 32x32. bf16 hi/lo out.
// =============================================================================
__global__ __launch_bounds__(256) void context_tc(
    const float* __restrict__ attn,
    const __nv_bfloat16* __restrict__ Vh, const __nv_bfloat16* __restrict__ Vl,
    __nv_bfloat16* __restrict__ Ch, __nv_bfloat16* __restrict__ Cl)
{
    __shared__ __align__(16) __nv_bfloat16 sPh[128][40];
    __shared__ __align__(16) __nv_bfloat16 sPl[128][40];
    __shared__ __align__(16) __nv_bfloat16 sVh[32][72];
    __shared__ __align__(16) __nv_bfloat16 sVl[32][72];

    const int tid  = threadIdx.x;
    const int lane = tid & 31;
    const int wid  = tid >> 5;
    const int wm   = wid >> 1;   // 0..3
    const int wn   = wid & 1;    // 0..1
    const int bhid = blockIdx.y;
    const int bidx = bhid >> 4;
    const int hidx = bhid & 15;
    const int s0   = blockIdx.x * 128;

    float acc[2][4][4];
#pragma unroll
    for (int im = 0; im < 2; im++)
#pragma unroll
        for (int jn = 0; jn < 4; jn++)
#pragma unroll
            for (int qq = 0; qq < 4; qq++) acc[im][jn][qq] = 0.f;

    for (int kt = 0; kt < SS; kt += 32) {
#pragma unroll
        for (int qq = 0; qq < 4; qq++) {
            int lin = tid + qq * 256;
            int srow = lin >> 3;
            int scol = (lin & 7) * 4;
            float4 pv = *(const float4*)(attn + ((size_t)bhid * SS + s0 + srow) * SS + kt + scol);
            __nv_bfloat16 ph0, ph1, ph2, ph3, pl0, pl1, pl2, pl3;
            splitbf(pv.x, ph0, pl0); splitbf(pv.y, ph1, pl1);
            splitbf(pv.z, ph2, pl2); splitbf(pv.w, ph3, pl3);
            *(__nv_bfloat162*)&sPh[srow][scol]     = __halves2bfloat162(ph0, ph1);
            *(__nv_bfloat162*)&sPh[srow][scol + 2] = __halves2bfloat162(ph2, ph3);
            *(__nv_bfloat162*)&sPl[srow][scol]     = __halves2bfloat162(pl0, pl1);
            *(__nv_bfloat162*)&sPl[srow][scol + 2] = __halves2bfloat162(pl2, pl3);
        }
        {
            int vrow = tid >> 3;
            int vcol = (tid & 7) * 8;
            size_t offV = ((size_t)bhid * SS + kt + vrow) * DK + vcol;
            *(uint4*)&sVh[vrow][vcol] = *(const uint4*)(Vh + offV);
            *(uint4*)&sVl[vrow][vcol] = *(const uint4*)(Vl + offV);
        }
        __syncthreads();

#pragma unroll
        for (int ks = 0; ks < 32; ks += 16) {
            uint32_t fAh[2][4], fAl[2][4], fBh[4][2], fBl[4][2];
#pragma unroll
            for (int mt = 0; mt < 2; mt++) {
                int ra = wm * 32 + mt * 16 + (lane & 15);
                int ca = ks + (lane >> 4) * 8;
                ldsm4(fAh[mt], smem_u32(&sPh[ra][ca]));
                ldsm4(fAl[mt], smem_u32(&sPl[ra][ca]));
            }
#pragma unroll
            for (int pp = 0; pp < 2; pp++) {
                int rb = ks + ((lane >> 3) & 1) * 8 + (lane & 7);
                int cb = wn * 32 + pp * 16 + (lane >> 4) * 8;
                ldsm4t(&fBh[2 * pp][0], smem_u32(&sVh[rb][cb]));
                ldsm4t(&fBl[2 * pp][0], smem_u32(&sVl[rb][cb]));
            }
#pragma unroll
            for (int mt = 0; mt < 2; mt++)
#pragma unroll
                for (int nt = 0; nt < 4; nt++) {
                    mma16816(acc[mt][nt], fAh[mt], fBh[nt]);
                    mma16816(acc[mt][nt], fAh[mt], fBl[nt]);
                    mma16816(acc[mt][nt], fAl[mt], fBh[nt]);
                }
        }
        __syncthreads();
    }

    const int cg = lane >> 2;
    const int ct = lane & 3;
#pragma unroll
    for (int mt = 0; mt < 2; mt++)
#pragma unroll
        for (int nt = 0; nt < 4; nt++) {
            int dd = wn * 32 + nt * 8 + 2 * ct;
#pragma unroll
            for (int hrow = 0; hrow < 2; hrow++) {
                int mmv = s0 + wm * 32 + mt * 16 + cg + hrow * 8;
                float ov0 = acc[mt][nt][hrow * 2 + 0];
                float ov1 = acc[mt][nt][hrow * 2 + 1];
                size_t oidx = ((size_t)(bidx * SS + mmv)) * DD + hidx * 64 + dd;
                __nv_bfloat16 zh0, zl0, zh1, zl1;
                splitbf(ov0, zh0, zl0);
                splitbf(ov1, zh1, zl1);
                *(__nv_bfloat162*)(Ch + oidx) = __halves2bfloat162(zh0, zh1);
                *(__nv_bfloat162*)(Cl + oidx) = __halves2bfloat162(zl0, zl1);
            }
        }
}

// =============================================================================
// LayerNorm: one block per row of 1024.
// =============================================================================
__global__ __launch_bounds__(256) void ln_kernel(
    const float* __restrict__ xin, const float* __restrict__ gamma,
    const float* __restrict__ beta, float* __restrict__ outp)
{
    __shared__ float sredA[8];
    __shared__ float sredB[8];
    const int row = blockIdx.x;
    const int tt = threadIdx.x;
    float4 lv = *(const float4*)(xin + (size_t)row * DD + tt * 4);

    float s1 = lv.x + lv.y + lv.z + lv.w;
    float s2 = lv.x * lv.x + lv.y * lv.y + lv.z * lv.z + lv.w * lv.w;
    s1 = wredSum(s1);
    s2 = wredSum(s2);
    if ((tt & 31) == 0) { sredA[tt >> 5] = s1; sredB[tt >> 5] = s2; }
    __syncthreads();
    if (tt < 32) {
        float ta = (tt < 8) ? sredA[tt] : 0.f;
        float tb = (tt < 8) ? sredB[tt] : 0.f;
        ta = wredSum(ta);
        tb = wredSum(tb);
        if (tt == 0) { sredA[0] = ta; sredB[0] = tb; }
    }
    __syncthreads();
    float mu  = sredA[0] * (1.0f / 1024.0f);
    float var = sredB[0] * (1.0f / 1024.0f) - mu * mu;
    float inv = rsqrtf(var + 1e-6f);

    float4 gv4 = *(const float4*)(gamma + tt * 4);
    float4 bv4 = *(const float4*)(beta + tt * 4);
    float4 ov4;
    ov4.x = (lv.x - mu) * inv * gv4.x + bv4.x;
    ov4.y = (lv.y - mu) * inv * gv4.y + bv4.y;
    ov4.z = (lv.z - mu) * inv * gv4.z + bv4.z;
    ov4.w = (lv.w - mu) * inv * gv4.w + bv4.w;
    *(float4*)(outp + (size_t)row * DD + tt * 4) = ov4;
}

// =============================================================================
extern "C" void kernel_launch(void* const* d_in, const int* in_sizes, int n_in,
                              void* d_out, int out_size)
{
    const float* in_q = (const float*)d_in[0];
    const float* in_k = (const float*)d_in[1];
    const float* in_v = (const float*)d_in[2];
    const unsigned char* in_mask = (const unsigned char*)d_in[3];
    const float* Wq   = (const float*)d_in[4];
    const float* bq   = (const float*)d_in[5];
    const float* Wk   = (const float*)d_in[6];
    const float* bk   = (const float*)d_in[7];
    const float* Wv   = (const float*)d_in[8];
    const float* bvv  = (const float*)d_in[9];
    const float* Wo   = (const float*)d_in[10];
    const float* bo   = (const float*)d_in[11];
    const float* ln_g = (const float*)d_in[12];
    const float* ln_b = (const float*)d_in[13];

    float* out_norm = (float*)d_out;
    float* attn = (float*)d_out + (size_t)MM * DD;

    __nv_bfloat16 *pqh, *pql, *pkh, *pkl, *pvh, *pvl;
    __nv_bfloat16 *pwqh, *pwql, *pwkh, *pwkl, *pwvh, *pwvl, *pwoh, *pwol;
    __nv_bfloat16 *pQh, *pQl, *pKh, *pKl, *pVh, *pVl, *pCh, *pCl;
    float *pX;
    cudaGetSymbolAddress((void**)&pqh, g_qh);
    cudaGetSymbolAddress((void**)&pql, g_ql);
    cudaGetSymbolAddress((void**)&pkh, g_kh);
    cudaGetSymbolAddress((void**)&pkl, g_kl);
    cudaGetSymbolAddress((void**)&pvh, g_vh);
    cudaGetSymbolAddress((void**)&pvl, g_vl);
    cudaGetSymbolAddress((void**)&pwqh, g_wqh);
    cudaGetSymbolAddress((void**)&pwql, g_wql);
    cudaGetSymbolAddress((void**)&pwkh, g_wkh);
    cudaGetSymbolAddress((void**)&pwkl, g_wkl);
    cudaGetSymbolAddress((void**)&pwvh, g_wvh);
    cudaGetSymbolAddress((void**)&pwvl, g_wvl);
    cudaGetSymbolAddress((void**)&pwoh, g_woh);
    cudaGetSymbolAddress((void**)&pwol, g_wol);
    cudaGetSymbolAddress((void**)&pQh, g_Qh);
    cudaGetSymbolAddress((void**)&pQl, g_Ql);
    cudaGetSymbolAddress((void**)&pKh, g_Kh);
    cudaGetSymbolAddress((void**)&pKl, g_Kl);
    cudaGetSymbolAddress((void**)&pVh, g_Vh);
    cudaGetSymbolAddress((void**)&pVl, g_Vl);
    cudaGetSymbolAddress((void**)&pCh, g_Ch);
    cudaGetSymbolAddress((void**)&pCl, g_Cl);
    cudaGetSymbolAddress((void**)&pX,  g_x);

    const int nAct = MM * DD;     // 4M
    const int nWt  = DD * DD;     // 1M
    split_kernel<<<1024, 256>>>(in_q, pqh, pql, nAct);
    split_kernel<<<1024, 256>>>(in_k, pkh, pkl, nAct);
    split_kernel<<<1024, 256>>>(in_v, pvh, pvl, nAct);
    split_kernel<<<512, 256>>>(Wq, pwqh, pwql, nWt);
    split_kernel<<<512, 256>>>(Wk, pwkh, pwkl, nWt);
    split_kernel<<<512, 256>>>(Wv, pwvh, pwvl, nWt);
    split_kernel<<<512, 256>>>(Wo, pwoh, pwol, nWt);

    dim3 gGemm(DD / 128, MM / 128);   // (8, 32)
    gemm_tc<1, 0><<<gGemm, 256>>>(pqh, pql, pwqh, pwql, bq, nullptr, pQh, pQl, nullptr);
    gemm_tc<1, 0><<<gGemm, 256>>>(pkh, pkl, pwkh, pwkl, bk, nullptr, pKh, pKl, nullptr);
    gemm_tc<1, 0><<<gGemm, 256>>>(pvh, pvl, pwvh, pwvl, bvv, nullptr, pVh, pVl, nullptr);

    dim3 gSc(SS / 128, SS / 128, BB * HH);   // (8,8,64)
    scores_tc<<<gSc, 256>>>(pQh, pQl, pKh, pKl, attn);

    softmax_kernel<<<BB * HH * SS, 256>>>(attn, in_mask);

    dim3 gCtx(SS / 128, BB * HH);            // (8,64)
    context_tc<<<gCtx, 256>>>(attn, pVh, pVl, pCh, pCl);

    gemm_tc<0, 1><<<gGemm, 256>>>(pCh, pCl, pwoh, pwol, bo, in_v, nullptr, nullptr, pX);

    ln_kernel<<<MM, 256>>>(pX, ln_g, ln_b, out_norm);
}

// round 4
// speedup vs baseline: 3.1715x; 1.0863x over previous
#include <cuda_runtime.h>
#include <cuda_bf16.h>
#include <cstdint>
#include <math.h>

#define BB 4
#define SS 1024
#define DD 1024
#define HH 16
#define DK 64
#define MM (BB*SS)   // 4096

// ---------------- scratch (__device__ globals; no allocation) ---------------
__device__ __nv_bfloat16 g_qh[(size_t)MM*DD];
__device__ __nv_bfloat16 g_ql[(size_t)MM*DD];
__device__ __nv_bfloat16 g_kh[(size_t)MM*DD];
__device__ __nv_bfloat16 g_kl[(size_t)MM*DD];
__device__ __nv_bfloat16 g_vh[(size_t)MM*DD];
__device__ __nv_bfloat16 g_vl[(size_t)MM*DD];
__device__ __nv_bfloat16 g_wqh[(size_t)DD*DD];
__device__ __nv_bfloat16 g_wql[(size_t)DD*DD];
__device__ __nv_bfloat16 g_wkh[(size_t)DD*DD];
__device__ __nv_bfloat16 g_wkl[(size_t)DD*DD];
__device__ __nv_bfloat16 g_wvh[(size_t)DD*DD];
__device__ __nv_bfloat16 g_wvl[(size_t)DD*DD];
__device__ __nv_bfloat16 g_woh[(size_t)DD*DD];
__device__ __nv_bfloat16 g_wol[(size_t)DD*DD];
__device__ __nv_bfloat16 g_Qh[(size_t)MM*DD];
__device__ __nv_bfloat16 g_Ql[(size_t)MM*DD];
__device__ __nv_bfloat16 g_Kh[(size_t)MM*DD];
__device__ __nv_bfloat16 g_Kl[(size_t)MM*DD];
__device__ __nv_bfloat16 g_Vh[(size_t)MM*DD];
__device__ __nv_bfloat16 g_Vl[(size_t)MM*DD];
__device__ __nv_bfloat16 g_Ch[(size_t)MM*DD];
__device__ __nv_bfloat16 g_Cl[(size_t)MM*DD];
__device__ float g_x[(size_t)MM*DD];

// ---------------- helpers ----------------------------------------------------
__device__ __forceinline__ uint32_t smem_u32(const void* ptr) {
    return (uint32_t)__cvta_generic_to_shared(ptr);
}
__device__ __forceinline__ void cpasync16(void* smemDst, const void* gsrc) {
    asm volatile("cp.async.cg.shared.global [%0], [%1], 16;"
                 :: "r"(smem_u32(smemDst)), "l"(gsrc));
}
__device__ __forceinline__ void ldsm4(uint32_t* dst, uint32_t addr) {
    asm volatile("ldmatrix.sync.aligned.m8n8.x4.shared.b16 {%0,%1,%2,%3},[%4];"
                 : "=r"(dst[0]), "=r"(dst[1]), "=r"(dst[2]), "=r"(dst[3]) : "r"(addr));
}
__device__ __forceinline__ void ldsm4t(uint32_t* dst, uint32_t addr) {
    asm volatile("ldmatrix.sync.aligned.m8n8.x4.trans.shared.b16 {%0,%1,%2,%3},[%4];"
                 : "=r"(dst[0]), "=r"(dst[1]), "=r"(dst[2]), "=r"(dst[3]) : "r"(addr));
}
__device__ __forceinline__ void mma16816(float* cc, const uint32_t* aa, const uint32_t* bb2) {
    asm volatile("mma.sync.aligned.m16n8k16.row.col.f32.bf16.bf16.f32 "
                 "{%0,%1,%2,%3},{%4,%5,%6,%7},{%8,%9},{%0,%1,%2,%3};"
                 : "+f"(cc[0]), "+f"(cc[1]), "+f"(cc[2]), "+f"(cc[3])
                 : "r"(aa[0]), "r"(aa[1]), "r"(aa[2]), "r"(aa[3]), "r"(bb2[0]), "r"(bb2[1]));
}
__device__ __forceinline__ void splitbf(float xin, __nv_bfloat16& ho, __nv_bfloat16& lo) {
    ho = __float2bfloat16(xin);
    lo = __float2bfloat16(xin - __bfloat162float(ho));
}
__device__ __forceinline__ float wredMax(float wv) {
#pragma unroll
    for (int wo = 16; wo; wo >>= 1) wv = fmaxf(wv, __shfl_xor_sync(0xffffffffu, wv, wo));
    return wv;
}
__device__ __forceinline__ float wredSum(float wv) {
#pragma unroll
    for (int wo = 16; wo; wo >>= 1) wv += __shfl_xor_sync(0xffffffffu, wv, wo);
    return wv;
}

// =============================================================================
// Merged split: up to 4 tensors of NELEM fp32 each -> bf16 hi/lo
// =============================================================================
struct SplitArgs {
    const float* src[4];
    __nv_bfloat16* dsth[4];
    __nv_bfloat16* dstl[4];
};

template<int NT, int NELEM>
__global__ __launch_bounds__(256) void split_multi(SplitArgs args)
{
    const int nF4 = NELEM / 4;
    int gi = blockIdx.x * 256 + threadIdx.x;
    const int gstride = gridDim.x * 256;
    for (; gi < NT * nF4; gi += gstride) {
        int ti = gi / nF4;
        int off4 = gi - ti * nF4;
        int ei = off4 * 4;
        float4 sv = *(const float4*)(args.src[ti] + ei);
        __nv_bfloat16 sh0, sh1, sh2, sh3, sl0, sl1, sl2, sl3;
        splitbf(sv.x, sh0, sl0); splitbf(sv.y, sh1, sl1);
        splitbf(sv.z, sh2, sl2); splitbf(sv.w, sh3, sl3);
        *(__nv_bfloat162*)(args.dsth[ti] + ei)     = __halves2bfloat162(sh0, sh1);
        *(__nv_bfloat162*)(args.dsth[ti] + ei + 2) = __halves2bfloat162(sh2, sh3);
        *(__nv_bfloat162*)(args.dstl[ti] + ei)     = __halves2bfloat162(sl0, sl1);
        *(__nv_bfloat162*)(args.dstl[ti] + ei + 2) = __halves2bfloat162(sl2, sl3);
    }
}

// =============================================================================
// GEMM: C = A[4096,1024] @ W^T (+bias) (+res).  A,W pre-split bf16 hi/lo.
// Block 128x128, BK=32, 2-stage cp.async pipeline, 8 warps (2x4), 3-pass MMA.
// Dynamic smem: 2 stages x 4 arrays x 128x40 bf16 = 81920 B.
// =============================================================================
#define GT_TILE 5120            // 128*40 elems per array
#define GT_STAGE (4*GT_TILE)    // elems per stage

__device__ __forceinline__ void gemm_fill(
    __nv_bfloat16* pool, int st, int tid, int m0, int n0, int kk,
    const __nv_bfloat16* __restrict__ Ah, const __nv_bfloat16* __restrict__ Al,
    const __nv_bfloat16* __restrict__ Wh, const __nv_bfloat16* __restrict__ Wl)
{
    __nv_bfloat16* base = pool + (size_t)st * GT_STAGE;
#pragma unroll
    for (int qq = 0; qq < 2; qq++) {
        int lin = tid + qq * 256;
        int srow = lin >> 2;
        int scol = (lin & 3) * 8;
        size_t offA = (size_t)(m0 + srow) * 1024 + kk + scol;
        size_t offW = (size_t)(n0 + srow) * 1024 + kk + scol;
        int sidx = srow * 40 + scol;
        cpasync16(base + 0 * GT_TILE + sidx, Ah + offA);
        cpasync16(base + 1 * GT_TILE + sidx, Al + offA);
        cpasync16(base + 2 * GT_TILE + sidx, Wh + offW);
        cpasync16(base + 3 * GT_TILE + sidx, Wl + offW);
    }
    asm volatile("cp.async.commit_group;");
}

template<int QKV_OUT, int ADD_RES>
__global__ __launch_bounds__(256) void gemm_tc(
    const __nv_bfloat16* __restrict__ Ah,
    const __nv_bfloat16* __restrict__ Al,
    const __nv_bfloat16* __restrict__ Wh,
    const __nv_bfloat16* __restrict__ Wl,
    const float* __restrict__ bias,
    const float* __restrict__ res,
    __nv_bfloat16* __restrict__ Oh,
    __nv_bfloat16* __restrict__ Ol,
    float* __restrict__ Of)
{
    extern __shared__ __align__(16) __nv_bfloat16 gpool[];

    const int tid  = threadIdx.x;
    const int lane = tid & 31;
    const int wid  = tid >> 5;
    const int wm   = wid >> 2;   // 0..1
    const int wn   = wid & 3;    // 0..3
    const int m0   = blockIdx.y * 128;
    const int n0   = blockIdx.x * 128;

    float acc[4][4][4];
#pragma unroll
    for (int im = 0; im < 4; im++)
#pragma unroll
        for (int jn = 0; jn < 4; jn++)
#pragma unroll
            for (int qq = 0; qq < 4; qq++) acc[im][jn][qq] = 0.f;

    gemm_fill(gpool, 0, tid, m0, n0, 0, Ah, Al, Wh, Wl);

    for (int it = 0; it < 32; it++) {
        if (it + 1 < 32) {
            gemm_fill(gpool, (it + 1) & 1, tid, m0, n0, (it + 1) * 32, Ah, Al, Wh, Wl);
            asm volatile("cp.async.wait_group 1;");
        } else {
            asm volatile("cp.async.wait_group 0;");
        }
        __syncthreads();

        __nv_bfloat16* sb = gpool + (size_t)(it & 1) * GT_STAGE;
        __nv_bfloat16* sAh = sb + 0 * GT_TILE;
        __nv_bfloat16* sAl = sb + 1 * GT_TILE;
        __nv_bfloat16* sWh = sb + 2 * GT_TILE;
        __nv_bfloat16* sWl = sb + 3 * GT_TILE;

#pragma unroll
        for (int ks = 0; ks < 32; ks += 16) {
            uint32_t fAh[4][4], fAl[4][4], fBh[4][2], fBl[4][2];
#pragma unroll
            for (int mt = 0; mt < 4; mt++) {
                int ra = wm * 64 + mt * 16 + (lane & 15);
                int ca = ks + (lane >> 4) * 8;
                ldsm4(fAh[mt], smem_u32(sAh + ra * 40 + ca));
                ldsm4(fAl[mt], smem_u32(sAl + ra * 40 + ca));
            }
#pragma unroll
            for (int pp = 0; pp < 2; pp++) {
                int rb = wn * 32 + pp * 16 + ((lane >> 4) & 1) * 8 + (lane & 7);
                int cb = ks + ((lane >> 3) & 1) * 8;
                ldsm4(&fBh[2 * pp][0], smem_u32(sWh + rb * 40 + cb));
                ldsm4(&fBl[2 * pp][0], smem_u32(sWl + rb * 40 + cb));
            }
#pragma unroll
            for (int mt = 0; mt < 4; mt++)
#pragma unroll
                for (int nt = 0; nt < 4; nt++) {
                    mma16816(acc[mt][nt], fAh[mt], fBh[nt]);
                    mma16816(acc[mt][nt], fAh[mt], fBl[nt]);
                    mma16816(acc[mt][nt], fAl[mt], fBh[nt]);
                }
        }
        __syncthreads();
    }

    const int cg = lane >> 2;
    const int ct = lane & 3;
#pragma unroll
    for (int mt = 0; mt < 4; mt++)
#pragma unroll
        for (int nt = 0; nt < 4; nt++) {
            int nn = n0 + wn * 32 + nt * 8 + 2 * ct;
            float bv0 = bias[nn];
            float bv1 = bias[nn + 1];
#pragma unroll
            for (int hrow = 0; hrow < 2; hrow++) {
                int mmv = m0 + wm * 64 + mt * 16 + cg + hrow * 8;
                float ov0 = acc[mt][nt][hrow * 2 + 0] + bv0;
                float ov1 = acc[mt][nt][hrow * 2 + 1] + bv1;
                if (ADD_RES) {
                    float2 rres = *(const float2*)(res + (size_t)mmv * 1024 + nn);
                    ov0 += rres.x;
                    ov1 += rres.y;
                }
                if (QKV_OUT) {
                    int obi = mmv >> 10;
                    int osi = mmv & 1023;
                    int ohh = nn >> 6;
                    int odd = nn & 63;
                    size_t oidx = (((size_t)(obi * HH + ohh)) * SS + osi) * DK + odd;
                    __nv_bfloat16 zh0, zl0, zh1, zl1;
                    splitbf(ov0, zh0, zl0);
                    splitbf(ov1, zh1, zl1);
                    *(__nv_bfloat162*)(Oh + oidx) = __halves2bfloat162(zh0, zh1);
                    *(__nv_bfloat162*)(Ol + oidx) = __halves2bfloat162(zl0, zl1);
                } else {
                    *(float2*)(Of + (size_t)mmv * 1024 + nn) = make_float2(ov0, ov1);
                }
            }
        }
}

// =============================================================================
// Scores: per head, S[s,t] = (Q[s,:].K[t,:]) / 8.  M=N=1024, K=64, 64 heads.
// Whole K=64 staged once via cp.async. Dynamic smem 4 x 128x72 bf16 = 73728 B.
// =============================================================================
#define SC_TILE 9216   // 128*72

__global__ __launch_bounds__(256) void scores_tc(
    const __nv_bfloat16* __restrict__ Qh, const __nv_bfloat16* __restrict__ Ql,
    const __nv_bfloat16* __restrict__ Kh, const __nv_bfloat16* __restrict__ Kl,
    float* __restrict__ attn)
{
    extern __shared__ __align__(16) __nv_bfloat16 spool[];
    __nv_bfloat16* sQh = spool + 0 * SC_TILE;
    __nv_bfloat16* sQl = spool + 1 * SC_TILE;
    __nv_bfloat16* sKh = spool + 2 * SC_TILE;
    __nv_bfloat16* sKl = spool + 3 * SC_TILE;

    const int tid  = threadIdx.x;
    const int lane = tid & 31;
    const int wid  = tid >> 5;
    const int wm   = wid >> 2;
    const int wn   = wid & 3;
    const int bhid = blockIdx.z;
    const int s0   = blockIdx.y * 128;
    const int t0   = blockIdx.x * 128;
    const size_t baseH = (size_t)bhid * SS * DK;

#pragma unroll
    for (int qq = 0; qq < 4; qq++) {
        int lin = tid + qq * 256;
        int srow = lin >> 3;
        int scol = (lin & 7) * 8;
        size_t offQ = baseH + (size_t)(s0 + srow) * DK + scol;
        size_t offK = baseH + (size_t)(t0 + srow) * DK + scol;
        int sidx = srow * 72 + scol;
        cpasync16(sQh + sidx, Qh + offQ);
        cpasync16(sQl + sidx, Ql + offQ);
        cpasync16(sKh + sidx, Kh + offK);
        cpasync16(sKl + sidx, Kl + offK);
    }
    asm volatile("cp.async.commit_group;");
    asm volatile("cp.async.wait_group 0;");
    __syncthreads();

    float acc[4][4][4];
#pragma unroll
    for (int im = 0; im < 4; im++)
#pragma unroll
        for (int jn = 0; jn < 4; jn++)
#pragma unroll
            for (int qq = 0; qq < 4; qq++) acc[im][jn][qq] = 0.f;

#pragma unroll
    for (int ks = 0; ks < 64; ks += 16) {
        uint32_t fAh[4][4], fAl[4][4], fBh[4][2], fBl[4][2];
#pragma unroll
        for (int mt = 0; mt < 4; mt++) {
            int ra = wm * 64 + mt * 16 + (lane & 15);
            int ca = ks + (lane >> 4) * 8;
            ldsm4(fAh[mt], smem_u32(sQh + ra * 72 + ca));
            ldsm4(fAl[mt], smem_u32(sQl + ra * 72 + ca));
        }
#pragma unroll
        for (int pp = 0; pp < 2; pp++) {
            int rb = wn * 32 + pp * 16 + ((lane >> 4) & 1) * 8 + (lane & 7);
            int cb = ks + ((lane >> 3) & 1) * 8;
            ldsm4(&fBh[2 * pp][0], smem_u32(sKh + rb * 72 + cb));
            ldsm4(&fBl[2 * pp][0], smem_u32(sKl + rb * 72 + cb));
        }
#pragma unroll
        for (int mt = 0; mt < 4; mt++)
#pragma unroll
            for (int nt = 0; nt < 4; nt++) {
                mma16816(acc[mt][nt], fAh[mt], fBh[nt]);
                mma16816(acc[mt][nt], fAh[mt], fBl[nt]);
                mma16816(acc[mt][nt], fAl[mt], fBh[nt]);
            }
    }

    const int cg = lane >> 2;
    const int ct = lane & 3;
#pragma unroll
    for (int mt = 0; mt < 4; mt++)
#pragma unroll
        for (int nt = 0; nt < 4; nt++) {
            int nn = t0 + wn * 32 + nt * 8 + 2 * ct;
#pragma unroll
            for (int hrow = 0; hrow < 2; hrow++) {
                int mmv = s0 + wm * 64 + mt * 16 + cg + hrow * 8;
                float ov0 = acc[mt][nt][hrow * 2 + 0] * 0.125f;
                float ov1 = acc[mt][nt][hrow * 2 + 1] * 0.125f;
                *(float2*)(attn + ((size_t)bhid * SS + mmv) * SS + nn) = make_float2(ov0, ov1);
            }
        }
}

// =============================================================================
// Softmax (in place, mask applied). One block per row.
// =============================================================================
__global__ __launch_bounds__(256) void softmax_kernel(
    float* __restrict__ attn, const unsigned char* __restrict__ mask)
{
    __shared__ float sred[8];
    const int row  = blockIdx.x;
    const int bhid = row >> 10;
    const int srow = row & 1023;
    const int bidx = bhid >> 4;
    float* prow = attn + (size_t)row * SS;
    const unsigned char* mrow = mask + ((size_t)(bidx * SS + srow)) * SS;
    const int tt = threadIdx.x;

    float4 xv = *(const float4*)(prow + tt * 4);
    uchar4 mk = *(const uchar4*)(mrow + tt * 4);
    if (mk.x) xv.x = -1e30f;
    if (mk.y) xv.y = -1e30f;
    if (mk.z) xv.z = -1e30f;
    if (mk.w) xv.w = -1e30f;

    float mx = fmaxf(fmaxf(xv.x, xv.y), fmaxf(xv.z, xv.w));
    mx = wredMax(mx);
    if ((tt & 31) == 0) sred[tt >> 5] = mx;
    __syncthreads();
    if (tt < 32) {
        float tmx = (tt < 8) ? sred[tt] : -1e30f;
        tmx = wredMax(tmx);
        if (tt == 0) sred[0] = tmx;
    }
    __syncthreads();
    mx = sred[0];

    float e0 = expf(xv.x - mx);
    float e1 = expf(xv.y - mx);
    float e2 = expf(xv.z - mx);
    float e3 = expf(xv.w - mx);
    float psum = e0 + e1 + e2 + e3;
    psum = wredSum(psum);
    __syncthreads();
    if ((tt & 31) == 0) sred[tt >> 5] = psum;
    __syncthreads();
    if (tt < 32) {
        float tsm = (tt < 8) ? sred[tt] : 0.f;
        tsm = wredSum(tsm);
        if (tt == 0) sred[0] = tsm;
    }
    __syncthreads();
    float inv = 1.0f / sred[0];

    *(float4*)(prow + tt * 4) = make_float4(e0 * inv, e1 * inv, e2 * inv, e3 * inv);
}

// =============================================================================
// Context: per head, ctx[s,d] = sum_t attn[s,t] * V[t,d].  M=1024,N=64,K=1024.
// =============================================================================
__global__ __launch_bounds__(256) void context_tc(
    const float* __restrict__ attn,
    const __nv_bfloat16* __restrict__ Vh, const __nv_bfloat16* __restrict__ Vl,
    __nv_bfloat16* __restrict__ Ch, __nv_bfloat16* __restrict__ Cl)
{
    __shared__ __align__(16) __nv_bfloat16 sPh[128][40];
    __shared__ __align__(16) __nv_bfloat16 sPl[128][40];
    __shared__ __align__(16) __nv_bfloat16 sVh[32][72];
    __shared__ __align__(16) __nv_bfloat16 sVl[32][72];

    const int tid  = threadIdx.x;
    const int lane = tid & 31;
    const int wid  = tid >> 5;
    const int wm   = wid >> 1;   // 0..3
    const int wn   = wid & 1;    // 0..1
    const int bhid = blockIdx.y;
    const int bidx = bhid >> 4;
    const int hidx = bhid & 15;
    const int s0   = blockIdx.x * 128;

    float acc[2][4][4];
#pragma unroll
    for (int im = 0; im < 2; im++)
#pragma unroll
        for (int jn = 0; jn < 4; jn++)
#pragma unroll
            for (int qq = 0; qq < 4; qq++) acc[im][jn][qq] = 0.f;

    for (int kt = 0; kt < SS; kt += 32) {
#pragma unroll
        for (int qq = 0; qq < 4; qq++) {
            int lin = tid + qq * 256;
            int srow = lin >> 3;
            int scol = (lin & 7) * 4;
            float4 pv = *(const float4*)(attn + ((size_t)bhid * SS + s0 + srow) * SS + kt + scol);
            __nv_bfloat16 ph0, ph1, ph2, ph3, pl0, pl1, pl2, pl3;
            splitbf(pv.x, ph0, pl0); splitbf(pv.y, ph1, pl1);
            splitbf(pv.z, ph2, pl2); splitbf(pv.w, ph3, pl3);
            *(__nv_bfloat162*)&sPh[srow][scol]     = __halves2bfloat162(ph0, ph1);
            *(__nv_bfloat162*)&sPh[srow][scol + 2] = __halves2bfloat162(ph2, ph3);
            *(__nv_bfloat162*)&sPl[srow][scol]     = __halves2bfloat162(pl0, pl1);
            *(__nv_bfloat162*)&sPl[srow][scol + 2] = __halves2bfloat162(pl2, pl3);
        }
        {
            int vrow = tid >> 3;
            int vcol = (tid & 7) * 8;
            size_t offV = ((size_t)bhid * SS + kt + vrow) * DK + vcol;
            *(uint4*)&sVh[vrow][vcol] = *(const uint4*)(Vh + offV);
            *(uint4*)&sVl[vrow][vcol] = *(const uint4*)(Vl + offV);
        }
        __syncthreads();

#pragma unroll
        for (int ks = 0; ks < 32; ks += 16) {
            uint32_t fAh[2][4], fAl[2][4], fBh[4][2], fBl[4][2];
#pragma unroll
            for (int mt = 0; mt < 2; mt++) {
                int ra = wm * 32 + mt * 16 + (lane & 15);
                int ca = ks + (lane >> 4) * 8;
                ldsm4(fAh[mt], smem_u32(&sPh[ra][ca]));
                ldsm4(fAl[mt], smem_u32(&sPl[ra][ca]));
            }
#pragma unroll
            for (int pp = 0; pp < 2; pp++) {
                int rb = ks + ((lane >> 3) & 1) * 8 + (lane & 7);
                int cb = wn * 32 + pp * 16 + (lane >> 4) * 8;
                ldsm4t(&fBh[2 * pp][0], smem_u32(&sVh[rb][cb]));
                ldsm4t(&fBl[2 * pp][0], smem_u32(&sVl[rb][cb]));
            }
#pragma unroll
            for (int mt = 0; mt < 2; mt++)
#pragma unroll
                for (int nt = 0; nt < 4; nt++) {
                    mma16816(acc[mt][nt], fAh[mt], fBh[nt]);
                    mma16816(acc[mt][nt], fAh[mt], fBl[nt]);
                    mma16816(acc[mt][nt], fAl[mt], fBh[nt]);
                }
        }
        __syncthreads();
    }

    const int cg = lane >> 2;
    const int ct = lane & 3;
#pragma unroll
    for (int mt = 0; mt < 2; mt++)
#pragma unroll
        for (int nt = 0; nt < 4; nt++) {
            int dd = wn * 32 + nt * 8 + 2 * ct;
#pragma unroll
            for (int hrow = 0; hrow < 2; hrow++) {
                int mmv = s0 + wm * 32 + mt * 16 + cg + hrow * 8;
                float ov0 = acc[mt][nt][hrow * 2 + 0];
                float ov1 = acc[mt][nt][hrow * 2 + 1];
                size_t oidx = ((size_t)(bidx * SS + mmv)) * DD + hidx * 64 + dd;
                __nv_bfloat16 zh0, zl0, zh1, zl1;
                splitbf(ov0, zh0, zl0);
                splitbf(ov1, zh1, zl1);
                *(__nv_bfloat162*)(Ch + oidx) = __halves2bfloat162(zh0, zh1);
                *(__nv_bfloat162*)(Cl + oidx) = __halves2bfloat162(zl0, zl1);
            }
        }
}

// =============================================================================
// LayerNorm: one block per row of 1024.
// =============================================================================
__global__ __launch_bounds__(256) void ln_kernel(
    const float* __restrict__ xin, const float* __restrict__ gamma,
    const float* __restrict__ beta, float* __restrict__ outp)
{
    __shared__ float sredA[8];
    __shared__ float sredB[8];
    const int row = blockIdx.x;
    const int tt = threadIdx.x;
    float4 lv = *(const float4*)(xin + (size_t)row * DD + tt * 4);

    float s1 = lv.x + lv.y + lv.z + lv.w;
    float s2 = lv.x * lv.x + lv.y * lv.y + lv.z * lv.z + lv.w * lv.w;
    s1 = wredSum(s1);
    s2 = wredSum(s2);
    if ((tt & 31) == 0) { sredA[tt >> 5] = s1; sredB[tt >> 5] = s2; }
    __syncthreads();
    if (tt < 32) {
        float ta = (tt < 8) ? sredA[tt] : 0.f;
        float tb = (tt < 8) ? sredB[tt] : 0.f;
        ta = wredSum(ta);
        tb = wredSum(tb);
        if (tt == 0) { sredA[0] = ta; sredB[0] = tb; }
    }
    __syncthreads();
    float mu  = sredA[0] * (1.0f / 1024.0f);
    float var = sredB[0] * (1.0f / 1024.0f) - mu * mu;
    float inv = rsqrtf(var + 1e-6f);

    float4 gv4 = *(const float4*)(gamma + tt * 4);
    float4 bv4 = *(const float4*)(beta + tt * 4);
    float4 ov4;
    ov4.x = (lv.x - mu) * inv * gv4.x + bv4.x;
    ov4.y = (lv.y - mu) * inv * gv4.y + bv4.y;
    ov4.z = (lv.z - mu) * inv * gv4.z + bv4.z;
    ov4.w = (lv.w - mu) * inv * gv4.w + bv4.w;
    *(float4*)(outp + (size_t)row * DD + tt * 4) = ov4;
}

// =============================================================================
extern "C" void kernel_launch(void* const* d_in, const int* in_sizes, int n_in,
                              void* d_out, int out_size)
{
    const float* in_q = (const float*)d_in[0];
    const float* in_k = (const float*)d_in[1];
    const float* in_v = (const float*)d_in[2];
    const unsigned char* in_mask = (const unsigned char*)d_in[3];
    const float* Wq   = (const float*)d_in[4];
    const float* bq   = (const float*)d_in[5];
    const float* Wk   = (const float*)d_in[6];
    const float* bk   = (const float*)d_in[7];
    const float* Wv   = (const float*)d_in[8];
    const float* bvv  = (const float*)d_in[9];
    const float* Wo   = (const float*)d_in[10];
    const float* bo   = (const float*)d_in[11];
    const float* ln_g = (const float*)d_in[12];
    const float* ln_b = (const float*)d_in[13];

    float* out_norm = (float*)d_out;
    float* attn = (float*)d_out + (size_t)MM * DD;

    __nv_bfloat16 *pqh, *pql, *pkh, *pkl, *pvh, *pvl;
    __nv_bfloat16 *pwqh, *pwql, *pwkh, *pwkl, *pwvh, *pwvl, *pwoh, *pwol;
    __nv_bfloat16 *pQh, *pQl, *pKh, *pKl, *pVh, *pVl, *pCh, *pCl;
    float *pX;
    cudaGetSymbolAddress((void**)&pqh, g_qh);
    cudaGetSymbolAddress((void**)&pql, g_ql);
    cudaGetSymbolAddress((void**)&pkh, g_kh);
    cudaGetSymbolAddress((void**)&pkl, g_kl);
    cudaGetSymbolAddress((void**)&pvh, g_vh);
    cudaGetSymbolAddress((void**)&pvl, g_vl);
    cudaGetSymbolAddress((void**)&pwqh, g_wqh);
    cudaGetSymbolAddress((void**)&pwql, g_wql);
    cudaGetSymbolAddress((void**)&pwkh, g_wkh);
    cudaGetSymbolAddress((void**)&pwkl, g_wkl);
    cudaGetSymbolAddress((void**)&pwvh, g_wvh);
    cudaGetSymbolAddress((void**)&pwvl, g_wvl);
    cudaGetSymbolAddress((void**)&pwoh, g_woh);
    cudaGetSymbolAddress((void**)&pwol, g_wol);
    cudaGetSymbolAddress((void**)&pQh, g_Qh);
    cudaGetSymbolAddress((void**)&pQl, g_Ql);
    cudaGetSymbolAddress((void**)&pKh, g_Kh);
    cudaGetSymbolAddress((void**)&pKl, g_Kl);
    cudaGetSymbolAddress((void**)&pVh, g_Vh);
    cudaGetSymbolAddress((void**)&pVl, g_Vl);
    cudaGetSymbolAddress((void**)&pCh, g_Ch);
    cudaGetSymbolAddress((void**)&pCl, g_Cl);
    cudaGetSymbolAddress((void**)&pX,  g_x);

    // dynamic smem opt-in (idempotent)
    cudaFuncSetAttribute(gemm_tc<1, 0>, cudaFuncAttributeMaxDynamicSharedMemorySize, 81920);
    cudaFuncSetAttribute(gemm_tc<0, 1>, cudaFuncAttributeMaxDynamicSharedMemorySize, 81920);
    cudaFuncSetAttribute(scores_tc, cudaFuncAttributeMaxDynamicSharedMemorySize, 73728);

    // --- splits (2 launches) ---
    SplitArgs sa;
    sa.src[0] = in_q;  sa.dsth[0] = pqh;  sa.dstl[0] = pql;
    sa.src[1] = in_k;  sa.dsth[1] = pkh;  sa.dstl[1] = pkl;
    sa.src[2] = in_v;  sa.dsth[2] = pvh;  sa.dstl[2] = pvl;
    sa.src[3] = in_q;  sa.dsth[3] = pqh;  sa.dstl[3] = pql;  // unused slot
    split_multi<3, MM * DD><<<2048, 256>>>(sa);

    SplitArgs sw;
    sw.src[0] = Wq;  sw.dsth[0] = pwqh;  sw.dstl[0] = pwql;
    sw.src[1] = Wk;  sw.dsth[1] = pwkh;  sw.dstl[1] = pwkl;
    sw.src[2] = Wv;  sw.dsth[2] = pwvh;  sw.dstl[2] = pwvl;
    sw.src[3] = Wo;  sw.dsth[3] = pwoh;  sw.dstl[3] = pwol;
    split_multi<4, DD * DD><<<2048, 256>>>(sw);

    dim3 gGemm(DD / 128, MM / 128);   // (8, 32)
    gemm_tc<1, 0><<<gGemm, 256, 81920>>>(pqh, pql, pwqh, pwql, bq, nullptr, pQh, pQl, nullptr);
    gemm_tc<1, 0><<<gGemm, 256, 81920>>>(pkh, pkl, pwkh, pwkl, bk, nullptr, pKh, pKl, nullptr);
    gemm_tc<1, 0><<<gGemm, 256, 81920>>>(pvh, pvl, pwvh, pwvl, bvv, nullptr, pVh, pVl, nullptr);

    dim3 gSc(SS / 128, SS / 128, BB * HH);   // (8,8,64)
    scores_tc<<<gSc, 256, 73728>>>(pQh, pQl, pKh, pKl, attn);

    softmax_kernel<<<BB * HH * SS, 256>>>(attn, in_mask);

    dim3 gCtx(SS / 128, BB * HH);            // (8,64)
    context_tc<<<gCtx, 256>>>(attn, pVh, pVl, pCh, pCl);

    gemm_tc<0, 1><<<gGemm, 256, 81920>>>(pCh, pCl, pwoh, pwol, bo, in_v, nullptr, nullptr, pX);

    ln_kernel<<<MM, 256>>>(pX, ln_g, ln_b, out_norm);
}